// round 9
// baseline (speedup 1.0000x reference)
#include <cuda_runtime.h>
#include <cuda_bf16.h>
#include <cstdint>

#define BB 64      // batch
#define TT 512     // timesteps
#define DD 256     // input dim
#define HH 1024    // hidden
#define GG 4096    // 4*H

// ---------------- scratch (device-global; no allocs allowed) ----------------
__device__ __align__(16) __nv_bfloat16 g_A0h[(size_t)TT * BB * DD];   // x hi plane [t*B+b][D]
__device__ __align__(16) __nv_bfloat16 g_A0l[(size_t)TT * BB * DD];   // x lo plane
__device__ __align__(16) __nv_bfloat16 g_wbh[(size_t)GG * HH];        // w_ih hi
__device__ __align__(16) __nv_bfloat16 g_wbl[(size_t)GG * HH];        // w_ih lo
__device__ __align__(16) float         g_xp[(size_t)TT * BB * GG];    // projections + biases
__device__ __align__(16) __nv_bfloat16 g_hseq_h[(size_t)TT * BB * HH];
__device__ __align__(16) __nv_bfloat16 g_hseq_l[(size_t)TT * BB * HH];
__device__ __align__(16) __nv_bfloat16 g_hbuf_h[2][BB * HH];
__device__ __align__(16) __nv_bfloat16 g_hbuf_l[2][BB * HH];
__device__ unsigned g_carr[TT * 8];   // per-step per-chunk readiness counters

#define NCTA 128     // recurrence CTAs (all resident, 1/SM)

// SMEM strides (word stride mod 32 == 4 -> conflict-free quad access)
#define RS_C 72      // gemm chunk row stride (bf16)
#define RS_C2 136    // recur h-chunk row stride (bf16): 68 words, 68%32=4
#define RS_W2 1032   // resident W row stride (bf16): 516 words, 516%32=4
#define RS_G 36      // gate row stride (fp32)
#define CH2  128     // recur k-chunk width
#define NCH2 8       // 1024/128 chunks

// recurrence SMEM layout (bytes)
#define OFF_WH 0                               // 32*RS_W2*2        = 66048
#define OFF_WL 66048                           // 66048             -> 132096
#define OFF_HH 132096                          // 2 bufs*64*RS_C2*2 = 34816
#define OFF_HL 166912                          // 34816             -> 201728
#define OFF_PS 201728                          // 64*RS_G*4         = 9216
#define OFF_GS 210944                          // 9216              -> 220160
#define OFF_CS 220160                          // 512*4             = 2048
#define SMEM_RECUR 222208

// ---------------- helpers ----------------
__device__ __forceinline__ void mma16816(float* c, uint32_t a0, uint32_t a1,
                                         uint32_t a2, uint32_t a3,
                                         uint32_t b0, uint32_t b1) {
    asm volatile(
        "mma.sync.aligned.m16n8k16.row.col.f32.bf16.bf16.f32 "
        "{%0,%1,%2,%3}, {%4,%5,%6,%7}, {%8,%9}, {%0,%1,%2,%3};"
        : "+f"(c[0]), "+f"(c[1]), "+f"(c[2]), "+f"(c[3])
        : "r"(a0), "r"(a1), "r"(a2), "r"(a3), "r"(b0), "r"(b1));
}
__device__ __forceinline__ void cp_async16(void* s, const void* g) {
    uint32_t sa = (uint32_t)__cvta_generic_to_shared(s);
    asm volatile("cp.async.cg.shared.global [%0], [%1], 16;\n" ::"r"(sa), "l"(g));
}
#define CP_COMMIT() asm volatile("cp.async.commit_group;\n")
#define CP_WAIT(N)  asm volatile("cp.async.wait_group %0;\n" ::"n"(N))

__device__ __forceinline__ float sigmoid_f(float x) { return 1.f / (1.f + __expf(-x)); }
__device__ __forceinline__ float tanh_f(float x) { return 2.f / (1.f + __expf(-2.f * x)) - 1.f; }

__device__ __forceinline__ void split_bf16(float v, __nv_bfloat16& hi, __nv_bfloat16& lo) {
    hi = __float2bfloat16(v);
    lo = __float2bfloat16(v - __bfloat162float(hi));
}

// spin until chunk ci of step t has all 16 producers done (reads are L2-coherent)
__device__ __forceinline__ void wait_chunk(int t, int ci) {
    const volatile unsigned* p = &g_carr[t * 8 + ci];
    while (*p < 16u) {}
    __threadfence();
}

// ---------------- prep: zero chunk flags + h buffers ----------------
__global__ void prep_kernel() {
    int idx = blockIdx.x * blockDim.x + threadIdx.x;
    int nflag = TT * 8;
    int nh = 2 * BB * HH;
    int total = nflag + 2 * nh;
    for (int i = idx; i < total; i += gridDim.x * blockDim.x) {
        if (i < nflag) g_carr[i] = 0u;
        else if (i < nflag + nh) ((__nv_bfloat16*)g_hbuf_h)[i - nflag] = __float2bfloat16(0.f);
        else ((__nv_bfloat16*)g_hbuf_l)[i - nflag - nh] = __float2bfloat16(0.f);
    }
}

// x[B][T][D] fp32 -> split planes [t*B+b][D]
__global__ void convert_x_kernel(const float* __restrict__ x) {
    size_t total = (size_t)BB * TT * DD;
    for (size_t i = (size_t)blockIdx.x * blockDim.x + threadIdx.x; i < total;
         i += (size_t)gridDim.x * blockDim.x) {
        int b = (int)(i / (TT * DD));
        int r = (int)(i % (TT * DD));
        int t = r / DD, d = r % DD;
        __nv_bfloat16 hi, lo;
        split_bf16(x[i], hi, lo);
        size_t o = ((size_t)t * BB + b) * DD + d;
        g_A0h[o] = hi;
        g_A0l[o] = lo;
    }
}

__global__ void convert_wih_kernel(const float* __restrict__ w, int n) {
    for (int i = blockIdx.x * blockDim.x + threadIdx.x; i < n; i += gridDim.x * blockDim.x) {
        __nv_bfloat16 hi, lo;
        split_bf16(w[i], hi, lo);
        g_wbh[i] = hi;
        g_wbl[i] = lo;
    }
}

// ---------------- projection GEMM (bf16x3): C = A.Wt + b1 + b2 ----------------
__global__ __launch_bounds__(256) void gemm_kernel(int layer, int K,
                                                   const float* __restrict__ bias1,
                                                   const float* __restrict__ bias2) {
    const __nv_bfloat16* Ah = (layer == 0) ? g_A0h : g_hseq_h;
    const __nv_bfloat16* Al = (layer == 0) ? g_A0l : g_hseq_l;
    __shared__ __nv_bfloat16 AsH[64][RS_C], AsL[64][RS_C];
    __shared__ __nv_bfloat16 BsH[64][RS_C], BsL[64][RS_C];

    int tid = threadIdx.x;
    int m0 = blockIdx.y * 64, n0 = blockIdx.x * 64;
    int lane = tid & 31, wid = tid >> 5;
    int gq = lane >> 2, tg = lane & 3;
    int mrow = (wid & 3) * 16;
    int nq = (wid >> 2) * 32;

    float acc[4][4];
#pragma unroll
    for (int a = 0; a < 4; a++)
#pragma unroll
        for (int b = 0; b < 4; b++) acc[a][b] = 0.f;

    for (int kt = 0; kt < K; kt += 64) {
#pragma unroll
        for (int f4 = tid; f4 < 512; f4 += 256) {
            int row = f4 >> 3, c = f4 & 7;
            *((float4*)&AsH[row][c * 8]) = *(const float4*)(Ah + (size_t)(m0 + row) * K + kt + c * 8);
            *((float4*)&AsL[row][c * 8]) = *(const float4*)(Al + (size_t)(m0 + row) * K + kt + c * 8);
            *((float4*)&BsH[row][c * 8]) = *(const float4*)(g_wbh + (size_t)(n0 + row) * K + kt + c * 8);
            *((float4*)&BsL[row][c * 8]) = *(const float4*)(g_wbl + (size_t)(n0 + row) * K + kt + c * 8);
        }
        __syncthreads();
#pragma unroll
        for (int kk = 0; kk < 64; kk += 16) {
            uint32_t ah0 = *(uint32_t*)&AsH[mrow + gq][kk + 2 * tg];
            uint32_t ah1 = *(uint32_t*)&AsH[mrow + gq + 8][kk + 2 * tg];
            uint32_t ah2 = *(uint32_t*)&AsH[mrow + gq][kk + 2 * tg + 8];
            uint32_t ah3 = *(uint32_t*)&AsH[mrow + gq + 8][kk + 2 * tg + 8];
            uint32_t al0 = *(uint32_t*)&AsL[mrow + gq][kk + 2 * tg];
            uint32_t al1 = *(uint32_t*)&AsL[mrow + gq + 8][kk + 2 * tg];
            uint32_t al2 = *(uint32_t*)&AsL[mrow + gq][kk + 2 * tg + 8];
            uint32_t al3 = *(uint32_t*)&AsL[mrow + gq + 8][kk + 2 * tg + 8];
#pragma unroll
            for (int nf = 0; nf < 4; nf++) {
                int n = nq + nf * 8 + gq;
                uint32_t bh0 = *(uint32_t*)&BsH[n][kk + 2 * tg];
                uint32_t bh1 = *(uint32_t*)&BsH[n][kk + 2 * tg + 8];
                uint32_t bl0 = *(uint32_t*)&BsL[n][kk + 2 * tg];
                uint32_t bl1 = *(uint32_t*)&BsL[n][kk + 2 * tg + 8];
                mma16816(acc[nf], ah0, ah1, ah2, ah3, bh0, bh1);
                mma16816(acc[nf], al0, al1, al2, al3, bh0, bh1);
                mma16816(acc[nf], ah0, ah1, ah2, ah3, bl0, bl1);
            }
        }
        __syncthreads();
    }

#pragma unroll
    for (int nf = 0; nf < 4; nf++) {
        int col = n0 + nq + nf * 8 + 2 * tg;
        float bs0 = bias1[col] + bias2[col];
        float bs1 = bias1[col + 1] + bias2[col + 1];
        int r0 = m0 + mrow + gq;
        g_xp[(size_t)r0 * GG + col] = acc[nf][0] + bs0;
        g_xp[(size_t)r0 * GG + col + 1] = acc[nf][1] + bs1;
        g_xp[(size_t)(r0 + 8) * GG + col] = acc[nf][2] + bs0;
        g_xp[(size_t)(r0 + 8) * GG + col + 1] = acc[nf][3] + bs1;
    }
}

// ---------------- persistent recurrence (bf16x3), 128 CTAs ----------------
// CTA owns 8 h-cols (32 gate rows: local row r = q*8+i -> global q*HH+j0+i).
// Both W planes SMEM-resident. h hi/lo streamed per 128-wide chunk (cp.async,
// double buffered). 8 warps = 4 m-warps x 2 k-groups; warp tile m16 x n32,
// k-slice 64 per chunk. Global barrier replaced by per-chunk readiness flags:
// chunk c of step t ready when its 16 producer CTAs bumped g_carr[t*8+c].
__global__ __launch_bounds__(256, 1) void recur_kernel(const float* __restrict__ w_hh) {
    extern __shared__ unsigned char smem[];
    __nv_bfloat16* Wh = (__nv_bfloat16*)(smem + OFF_WH);
    __nv_bfloat16* Wl = (__nv_bfloat16*)(smem + OFF_WL);
    __nv_bfloat16* HsH = (__nv_bfloat16*)(smem + OFF_HH);   // 2 bufs of 64*RS_C2
    __nv_bfloat16* HsL = (__nv_bfloat16*)(smem + OFF_HL);
    float* PS = (float*)(smem + OFF_PS);                    // 1 partial set
    float* Gs = (float*)(smem + OFF_GS);
    float* Cs = (float*)(smem + OFF_CS);

    int tid = threadIdx.x;
    int j0 = blockIdx.x * 8;
    int mychunk = blockIdx.x >> 4;

    // Preload resident W slice (both planes), split from fp32
    for (int idx = tid; idx < 32 * 1024; idx += 256) {
        int r = idx >> 10, k = idx & 1023;
        int q = r >> 3, i = r & 7;
        float v = w_hh[(size_t)(q * HH + j0 + i) * HH + k];
        __nv_bfloat16 hi, lo;
        split_bf16(v, hi, lo);
        Wh[r * RS_W2 + k] = hi;
        Wl[r * RS_W2 + k] = lo;
    }
    for (int idx = tid; idx < 512; idx += 256) Cs[idx] = 0.f;
    __syncthreads();

    int lane = tid & 31, wid = tid >> 5;
    int gq = lane >> 2, tg = lane & 3;
    int mw = wid & 3;            // m-warp: rows mw*16..mw*16+15
    int kg = wid >> 2;           // k-group 0/1: k-slice kg*64 within chunk
    int r0 = mw * 16 + gq;
    int kks = kg * 64;

    for (int t = 0; t < TT; t++) {
        const __nv_bfloat16* rbh = g_hbuf_h[(t + 1) & 1];
        const __nv_bfloat16* rbl = g_hbuf_l[(t + 1) & 1];
        __nv_bfloat16* wbh = g_hbuf_h[t & 1];
        __nv_bfloat16* wbl = g_hbuf_l[t & 1];

        float acc[4][4];
#pragma unroll
        for (int a = 0; a < 4; a++)
#pragma unroll
            for (int b = 0; b < 4; b++) acc[a][b] = 0.f;

        // issue chunk 0 (gated on producers of step t-1)
        {
            if (t > 0) wait_chunk(t - 1, 0);
#pragma unroll
            for (int s = tid; s < 2048; s += 256) {
                int plane = s >> 10, r = (s >> 4) & 63, seg = s & 15;
                if (plane == 0)
                    cp_async16(HsH + r * RS_C2 + seg * 8, rbh + (size_t)r * HH + seg * 8);
                else
                    cp_async16(HsL + r * RS_C2 + seg * 8, rbl + (size_t)r * HH + seg * 8);
            }
            CP_COMMIT();
        }

        for (int ci = 0; ci < NCH2; ci++) {
            if (ci + 1 < NCH2) {
                if (t > 0) wait_chunk(t - 1, ci + 1);
                int kc = (ci + 1) * CH2;
                int bo = ((ci + 1) & 1) * 64 * RS_C2;
#pragma unroll
                for (int s = tid; s < 2048; s += 256) {
                    int plane = s >> 10, r = (s >> 4) & 63, seg = s & 15;
                    if (plane == 0)
                        cp_async16(HsH + bo + r * RS_C2 + seg * 8, rbh + (size_t)r * HH + kc + seg * 8);
                    else
                        cp_async16(HsL + bo + r * RS_C2 + seg * 8, rbl + (size_t)r * HH + kc + seg * 8);
                }
                CP_COMMIT();
                CP_WAIT(1);
            } else {
                CP_WAIT(0);
            }
            __syncthreads();

            int bo = (ci & 1) * 64 * RS_C2;
            const __nv_bfloat16* hH = HsH + bo;
            const __nv_bfloat16* hL = HsL + bo;
#pragma unroll
            for (int kk = 0; kk < 64; kk += 16) {
                int kl = kks + kk;               // k within chunk
                int kw = ci * CH2 + kl;          // global k for resident W
                uint32_t ah0 = *(uint32_t*)&hH[r0 * RS_C2 + kl + 2 * tg];
                uint32_t ah1 = *(uint32_t*)&hH[(r0 + 8) * RS_C2 + kl + 2 * tg];
                uint32_t ah2 = *(uint32_t*)&hH[r0 * RS_C2 + kl + 2 * tg + 8];
                uint32_t ah3 = *(uint32_t*)&hH[(r0 + 8) * RS_C2 + kl + 2 * tg + 8];
                uint32_t al0 = *(uint32_t*)&hL[r0 * RS_C2 + kl + 2 * tg];
                uint32_t al1 = *(uint32_t*)&hL[(r0 + 8) * RS_C2 + kl + 2 * tg];
                uint32_t al2 = *(uint32_t*)&hL[r0 * RS_C2 + kl + 2 * tg + 8];
                uint32_t al3 = *(uint32_t*)&hL[(r0 + 8) * RS_C2 + kl + 2 * tg + 8];
#pragma unroll
                for (int nf = 0; nf < 4; nf++) {
                    int n = nf * 8 + gq;
                    uint32_t bh0 = *(uint32_t*)&Wh[n * RS_W2 + kw + 2 * tg];
                    uint32_t bh1 = *(uint32_t*)&Wh[n * RS_W2 + kw + 2 * tg + 8];
                    uint32_t bl0 = *(uint32_t*)&Wl[n * RS_W2 + kw + 2 * tg];
                    uint32_t bl1 = *(uint32_t*)&Wl[n * RS_W2 + kw + 2 * tg + 8];
                    mma16816(acc[nf], ah0, ah1, ah2, ah3, bh0, bh1);
                    mma16816(acc[nf], al0, al1, al2, al3, bh0, bh1);
                    mma16816(acc[nf], ah0, ah1, ah2, ah3, bl0, bl1);
                }
            }
            __syncthreads();
        }

        // k-group reduction: kg=1 dumps partials, kg=0 combines into Gs
        if (kg == 1) {
#pragma unroll
            for (int nf = 0; nf < 4; nf++) {
                int col = nf * 8 + 2 * tg;
                PS[r0 * RS_G + col] = acc[nf][0];
                PS[r0 * RS_G + col + 1] = acc[nf][1];
                PS[(r0 + 8) * RS_G + col] = acc[nf][2];
                PS[(r0 + 8) * RS_G + col + 1] = acc[nf][3];
            }
        }
        __syncthreads();
        if (kg == 0) {
#pragma unroll
            for (int nf = 0; nf < 4; nf++) {
                int col = nf * 8 + 2 * tg;
                Gs[r0 * RS_G + col] = acc[nf][0] + PS[r0 * RS_G + col];
                Gs[r0 * RS_G + col + 1] = acc[nf][1] + PS[r0 * RS_G + col + 1];
                Gs[(r0 + 8) * RS_G + col] = acc[nf][2] + PS[(r0 + 8) * RS_G + col];
                Gs[(r0 + 8) * RS_G + col + 1] = acc[nf][3] + PS[(r0 + 8) * RS_G + col + 1];
            }
        }
        __syncthreads();

        // cell update: 64 batches x 8 cols
        const float* xpt = g_xp + (size_t)t * BB * GG;
#pragma unroll
        for (int e = tid; e < 512; e += 256) {
            int b = e >> 3, i = e & 7;
            float gi = Gs[b * RS_G + i]      + xpt[(size_t)b * GG + j0 + i];
            float gf = Gs[b * RS_G + 8 + i]  + xpt[(size_t)b * GG + HH + j0 + i];
            float gg = Gs[b * RS_G + 16 + i] + xpt[(size_t)b * GG + 2 * HH + j0 + i];
            float go = Gs[b * RS_G + 24 + i] + xpt[(size_t)b * GG + 3 * HH + j0 + i];
            float si = sigmoid_f(gi);
            float sf = sigmoid_f(gf);
            float sg = tanh_f(gg);
            float so = sigmoid_f(go);
            float c = sf * Cs[e] + si * sg;
            Cs[e] = c;
            float h = so * tanh_f(c);
            __nv_bfloat16 hi, lo;
            split_bf16(h, hi, lo);
            size_t po = (size_t)b * HH + j0 + i;
            wbh[po] = hi;
            wbl[po] = lo;
            size_t so2 = ((size_t)t * BB + b) * HH + j0 + i;
            g_hseq_h[so2] = hi;
            g_hseq_l[so2] = lo;
        }
        __syncthreads();

        // publish this CTA's chunk contribution for step t
        if (tid == 0) {
            __threadfence();
            atomicAdd(&g_carr[t * 8 + mychunk], 1u);
        }
    }
}

// ---------------- final linear ----------------
__global__ void final_kernel(const float* __restrict__ w_lin,
                             const float* __restrict__ b_lin,
                             float* __restrict__ out) {
    int b = blockIdx.x;
    __shared__ float red[256];
    float s = 0.f;
    size_t base = ((size_t)(TT - 1) * BB + b) * HH;
    for (int i = threadIdx.x; i < HH; i += 256) {
        float h = __bfloat162float(g_hseq_h[base + i]) + __bfloat162float(g_hseq_l[base + i]);
        s += h * w_lin[i];
    }
    red[threadIdx.x] = s;
    __syncthreads();
    for (int st = 128; st > 0; st >>= 1) {
        if (threadIdx.x < st) red[threadIdx.x] += red[threadIdx.x + st];
        __syncthreads();
    }
    if (threadIdx.x == 0) out[b] = red[0] + b_lin[0];
}

// ---------------- launch ----------------
extern "C" void kernel_launch(void* const* d_in, const int* in_sizes, int n_in,
                              void* d_out, int out_size) {
    const float* x     = (const float*)d_in[0];
    const float* w_ih0 = (const float*)d_in[1];
    const float* w_hh0 = (const float*)d_in[2];
    const float* b_ih0 = (const float*)d_in[3];
    const float* b_hh0 = (const float*)d_in[4];
    const float* w_ih1 = (const float*)d_in[5];
    const float* w_hh1 = (const float*)d_in[6];
    const float* b_ih1 = (const float*)d_in[7];
    const float* b_hh1 = (const float*)d_in[8];
    const float* w_lin = (const float*)d_in[9];
    const float* b_lin = (const float*)d_in[10];
    float* out = (float*)d_out;

    cudaFuncSetAttribute(recur_kernel, cudaFuncAttributeMaxDynamicSharedMemorySize,
                         SMEM_RECUR);

    // layer 0
    prep_kernel<<<256, 256>>>();
    convert_x_kernel<<<2048, 256>>>(x);
    convert_wih_kernel<<<1024, 256>>>(w_ih0, GG * DD);
    gemm_kernel<<<dim3(64, 512), 256>>>(0, DD, b_ih0, b_hh0);
    recur_kernel<<<NCTA, 256, SMEM_RECUR>>>(w_hh0);

    // layer 1
    prep_kernel<<<256, 256>>>();
    convert_wih_kernel<<<4096, 256>>>(w_ih1, GG * HH);
    gemm_kernel<<<dim3(64, 512), 256>>>(1, HH, b_ih1, b_hh1);
    recur_kernel<<<NCTA, 256, SMEM_RECUR>>>(w_hh1);

    // output head
    final_kernel<<<64, 256>>>(w_lin, b_lin, out);
}

// round 13
// speedup vs baseline: 1.3774x; 1.3774x over previous
#include <cuda_runtime.h>
#include <cuda_bf16.h>
#include <cstdint>

#define BB 64      // batch
#define TT 512     // timesteps
#define DD 256     // input dim
#define HH 1024    // hidden
#define GG 4096    // 4*H

// ---------------- scratch (device-global; no allocs allowed) ----------------
__device__ __align__(16) __nv_bfloat16 g_A0h[(size_t)TT * BB * DD];   // x hi plane [t*B+b][D]
__device__ __align__(16) __nv_bfloat16 g_A0l[(size_t)TT * BB * DD];   // x lo plane
__device__ __align__(16) __nv_bfloat16 g_wbh[(size_t)GG * HH];        // w_ih hi
__device__ __align__(16) __nv_bfloat16 g_wbl[(size_t)GG * HH];        // w_ih lo
__device__ __align__(16) float         g_xp[(size_t)TT * BB * GG];    // projections + biases
__device__ __align__(16) __nv_bfloat16 g_hseq_h[(size_t)TT * BB * HH];
__device__ __align__(16) __nv_bfloat16 g_hseq_l[(size_t)TT * BB * HH];
__device__ __align__(16) __nv_bfloat16 g_hbuf_h[2][BB * HH];
__device__ __align__(16) __nv_bfloat16 g_hbuf_l[2][BB * HH];
__device__ volatile unsigned g_flags[128 * 32];   // per-CTA step flags, 128B stride

#define NCTA 128     // recurrence CTAs (all resident, 1/SM)

// SMEM strides (word stride mod 32 == 4 -> conflict-free quad access)
#define RS_C 72      // gemm chunk row stride (bf16)
#define RS_C2 136    // recur h-chunk row stride (bf16): 68 words, 68%32=4
#define RS_W2 1032   // resident W row stride (bf16): 516 words, 516%32=4
#define RS_G 36      // gate row stride (fp32)
#define CH2  128     // recur k-chunk width
#define NCH2 8       // 1024/128 chunks

// recurrence SMEM layout (bytes)
#define OFF_WH 0                               // 2 planes * 32*RS_W2*2 = 132096
#define OFF_HH 132096                          // 2 bufs*64*RS_C2*2 = 34816
#define OFF_HL 166912                          // -> 201728
#define OFF_PS 201728                          // 64*RS_G*4 = 9216
#define OFF_GS 210944                          // 9216
#define OFF_CS 220160                          // 512*4 = 2048
#define OFF_XP 222208                          // 64*RS_G*4 = 9216
#define SMEM_RECUR 231424

// ---------------- helpers ----------------
__device__ __forceinline__ void mma16816(float* c, uint32_t a0, uint32_t a1,
                                         uint32_t a2, uint32_t a3,
                                         uint32_t b0, uint32_t b1) {
    asm volatile(
        "mma.sync.aligned.m16n8k16.row.col.f32.bf16.bf16.f32 "
        "{%0,%1,%2,%3}, {%4,%5,%6,%7}, {%8,%9}, {%0,%1,%2,%3};"
        : "+f"(c[0]), "+f"(c[1]), "+f"(c[2]), "+f"(c[3])
        : "r"(a0), "r"(a1), "r"(a2), "r"(a3), "r"(b0), "r"(b1));
}
__device__ __forceinline__ void cp_async16(void* s, const void* g) {
    uint32_t sa = (uint32_t)__cvta_generic_to_shared(s);
    asm volatile("cp.async.cg.shared.global [%0], [%1], 16;\n" ::"r"(sa), "l"(g));
}
#define CP_COMMIT() asm volatile("cp.async.commit_group;\n")
#define CP_WAIT(N)  asm volatile("cp.async.wait_group %0;\n" ::"n"(N))

__device__ __forceinline__ float sigmoid_f(float x) { return 1.f / (1.f + __expf(-x)); }
__device__ __forceinline__ float tanh_f(float x) { return 2.f / (1.f + __expf(-2.f * x)) - 1.f; }

__device__ __forceinline__ void split_bf16(float v, __nv_bfloat16& hi, __nv_bfloat16& lo) {
    hi = __float2bfloat16(v);
    lo = __float2bfloat16(v - __bfloat162float(hi));
}

// ---------------- prep: zero flags + h buffers ----------------
__global__ void prep_kernel() {
    int idx = blockIdx.x * blockDim.x + threadIdx.x;
    int nflag = 128 * 32;
    int nh = 2 * BB * HH;
    int total = nflag + 2 * nh;
    for (int i = idx; i < total; i += gridDim.x * blockDim.x) {
        if (i < nflag) g_flags[i] = 0u;
        else if (i < nflag + nh) ((__nv_bfloat16*)g_hbuf_h)[i - nflag] = __float2bfloat16(0.f);
        else ((__nv_bfloat16*)g_hbuf_l)[i - nflag - nh] = __float2bfloat16(0.f);
    }
}

// x[B][T][D] fp32 -> split planes [t*B+b][D]
__global__ void convert_x_kernel(const float* __restrict__ x) {
    size_t total = (size_t)BB * TT * DD;
    for (size_t i = (size_t)blockIdx.x * blockDim.x + threadIdx.x; i < total;
         i += (size_t)gridDim.x * blockDim.x) {
        int b = (int)(i / (TT * DD));
        int r = (int)(i % (TT * DD));
        int t = r / DD, d = r % DD;
        __nv_bfloat16 hi, lo;
        split_bf16(x[i], hi, lo);
        size_t o = ((size_t)t * BB + b) * DD + d;
        g_A0h[o] = hi;
        g_A0l[o] = lo;
    }
}

__global__ void convert_wih_kernel(const float* __restrict__ w, int n) {
    for (int i = blockIdx.x * blockDim.x + threadIdx.x; i < n; i += gridDim.x * blockDim.x) {
        __nv_bfloat16 hi, lo;
        split_bf16(w[i], hi, lo);
        g_wbh[i] = hi;
        g_wbl[i] = lo;
    }
}

// ---------------- projection GEMM (bf16x3): C = A.Wt + b1 + b2 ----------------
__global__ __launch_bounds__(256) void gemm_kernel(int layer, int K,
                                                   const float* __restrict__ bias1,
                                                   const float* __restrict__ bias2) {
    const __nv_bfloat16* Ah = (layer == 0) ? g_A0h : g_hseq_h;
    const __nv_bfloat16* Al = (layer == 0) ? g_A0l : g_hseq_l;
    __shared__ __nv_bfloat16 AsH[64][RS_C], AsL[64][RS_C];
    __shared__ __nv_bfloat16 BsH[64][RS_C], BsL[64][RS_C];

    int tid = threadIdx.x;
    int m0 = blockIdx.y * 64, n0 = blockIdx.x * 64;
    int lane = tid & 31, wid = tid >> 5;
    int gq = lane >> 2, tg = lane & 3;
    int mrow = (wid & 3) * 16;
    int nq = (wid >> 2) * 32;

    float acc[4][4];
#pragma unroll
    for (int a = 0; a < 4; a++)
#pragma unroll
        for (int b = 0; b < 4; b++) acc[a][b] = 0.f;

    for (int kt = 0; kt < K; kt += 64) {
#pragma unroll
        for (int f4 = tid; f4 < 512; f4 += 256) {
            int row = f4 >> 3, c = f4 & 7;
            *((float4*)&AsH[row][c * 8]) = *(const float4*)(Ah + (size_t)(m0 + row) * K + kt + c * 8);
            *((float4*)&AsL[row][c * 8]) = *(const float4*)(Al + (size_t)(m0 + row) * K + kt + c * 8);
            *((float4*)&BsH[row][c * 8]) = *(const float4*)(g_wbh + (size_t)(n0 + row) * K + kt + c * 8);
            *((float4*)&BsL[row][c * 8]) = *(const float4*)(g_wbl + (size_t)(n0 + row) * K + kt + c * 8);
        }
        __syncthreads();
#pragma unroll
        for (int kk = 0; kk < 64; kk += 16) {
            uint32_t ah0 = *(uint32_t*)&AsH[mrow + gq][kk + 2 * tg];
            uint32_t ah1 = *(uint32_t*)&AsH[mrow + gq + 8][kk + 2 * tg];
            uint32_t ah2 = *(uint32_t*)&AsH[mrow + gq][kk + 2 * tg + 8];
            uint32_t ah3 = *(uint32_t*)&AsH[mrow + gq + 8][kk + 2 * tg + 8];
            uint32_t al0 = *(uint32_t*)&AsL[mrow + gq][kk + 2 * tg];
            uint32_t al1 = *(uint32_t*)&AsL[mrow + gq + 8][kk + 2 * tg];
            uint32_t al2 = *(uint32_t*)&AsL[mrow + gq][kk + 2 * tg + 8];
            uint32_t al3 = *(uint32_t*)&AsL[mrow + gq + 8][kk + 2 * tg + 8];
#pragma unroll
            for (int nf = 0; nf < 4; nf++) {
                int n = nq + nf * 8 + gq;
                uint32_t bh0 = *(uint32_t*)&BsH[n][kk + 2 * tg];
                uint32_t bh1 = *(uint32_t*)&BsH[n][kk + 2 * tg + 8];
                uint32_t bl0 = *(uint32_t*)&BsL[n][kk + 2 * tg];
                uint32_t bl1 = *(uint32_t*)&BsL[n][kk + 2 * tg + 8];
                mma16816(acc[nf], ah0, ah1, ah2, ah3, bh0, bh1);
                mma16816(acc[nf], al0, al1, al2, al3, bh0, bh1);
                mma16816(acc[nf], ah0, ah1, ah2, ah3, bl0, bl1);
            }
        }
        __syncthreads();
    }

#pragma unroll
    for (int nf = 0; nf < 4; nf++) {
        int col = n0 + nq + nf * 8 + 2 * tg;
        float bs0 = bias1[col] + bias2[col];
        float bs1 = bias1[col + 1] + bias2[col + 1];
        int r0 = m0 + mrow + gq;
        g_xp[(size_t)r0 * GG + col] = acc[nf][0] + bs0;
        g_xp[(size_t)r0 * GG + col + 1] = acc[nf][1] + bs1;
        g_xp[(size_t)(r0 + 8) * GG + col] = acc[nf][2] + bs0;
        g_xp[(size_t)(r0 + 8) * GG + col + 1] = acc[nf][3] + bs1;
    }
}

// ---------------- persistent recurrence (bf16x3), 128 CTAs ----------------
// CTA owns 8 h-cols (32 gate rows). Both W planes SMEM-resident. h hi/lo
// streamed per 128-wide chunk (cp.async, double buffered, both pre-issued).
// 8 warps = 4 m-warps x 2 k-groups; warp tile m16 x n32, k-slice 64.
// Step barrier: per-CTA spread flags (plain release store + 128-thread poll).
// xp(t) prefetched to SMEM alongside chunk 0.
__global__ __launch_bounds__(256, 1) void recur_kernel(const float* __restrict__ w_hh) {
    extern __shared__ unsigned char smem[];
    __nv_bfloat16* Wh = (__nv_bfloat16*)(smem + OFF_WH);
    __nv_bfloat16* Wl = (__nv_bfloat16*)(smem + OFF_WH + 66048);
    __nv_bfloat16* HsH = (__nv_bfloat16*)(smem + OFF_HH);   // 2 bufs of 64*RS_C2
    __nv_bfloat16* HsL = (__nv_bfloat16*)(smem + OFF_HL);
    float* PS = (float*)(smem + OFF_PS);                    // 1 partial set
    float* Gs = (float*)(smem + OFF_GS);
    float* Cs = (float*)(smem + OFF_CS);
    float* XPs = (float*)(smem + OFF_XP);                   // xp(t) staged

    int tid = threadIdx.x;
    int j0 = blockIdx.x * 8;

    // Preload resident W slice (both planes), split from fp32
    for (int idx = tid; idx < 32 * 1024; idx += 256) {
        int r = idx >> 10, k = idx & 1023;
        int q = r >> 3, i = r & 7;
        float v = w_hh[(size_t)(q * HH + j0 + i) * HH + k];
        __nv_bfloat16 hi, lo;
        split_bf16(v, hi, lo);
        Wh[r * RS_W2 + k] = hi;
        Wl[r * RS_W2 + k] = lo;
    }
    for (int idx = tid; idx < 512; idx += 256) Cs[idx] = 0.f;
    __syncthreads();

    int lane = tid & 31, wid = tid >> 5;
    int gq = lane >> 2, tg = lane & 3;
    int mw = wid & 3;            // m-warp: rows mw*16..mw*16+15
    int kg = wid >> 2;           // k-group 0/1: k-slice kg*64 within chunk
    int r0 = mw * 16 + gq;
    int kks = kg * 64;

    for (int t = 0; t < TT; t++) {
        // step barrier: wait for all CTAs to have finished step t-1
        if (t > 0) {
            if (tid < NCTA) {
                while (g_flags[tid * 32] < (unsigned)t) {}
            }
            __syncthreads();
        }

        const __nv_bfloat16* rbh = g_hbuf_h[(t + 1) & 1];
        const __nv_bfloat16* rbl = g_hbuf_l[(t + 1) & 1];
        __nv_bfloat16* wbh = g_hbuf_h[t & 1];
        __nv_bfloat16* wbl = g_hbuf_l[t & 1];
        const float* xpt = g_xp + (size_t)t * BB * GG;

        float acc[4][4];
#pragma unroll
        for (int a = 0; a < 4; a++)
#pragma unroll
            for (int b = 0; b < 4; b++) acc[a][b] = 0.f;

        // pre-issue chunk 0 (+ xp prefetch) and chunk 1
        {
#pragma unroll
            for (int s = tid; s < 2048; s += 256) {
                int plane = s >> 10, r = (s >> 4) & 63, seg = s & 15;
                if (plane == 0)
                    cp_async16(HsH + r * RS_C2 + seg * 8, rbh + (size_t)r * HH + seg * 8);
                else
                    cp_async16(HsL + r * RS_C2 + seg * 8, rbl + (size_t)r * HH + seg * 8);
            }
            // xp(t): 64 b x 4 gates x 8 floats -> XPs[b*RS_G + gate*8 + i]
#pragma unroll
            for (int s = tid; s < 512; s += 256) {
                int b = s >> 3, gate = (s >> 1) & 3, half = s & 1;
                cp_async16(XPs + b * RS_G + gate * 8 + half * 4,
                           xpt + (size_t)b * GG + gate * HH + j0 + half * 4);
            }
            CP_COMMIT();
            int bo = 64 * RS_C2;
#pragma unroll
            for (int s = tid; s < 2048; s += 256) {
                int plane = s >> 10, r = (s >> 4) & 63, seg = s & 15;
                if (plane == 0)
                    cp_async16(HsH + bo + r * RS_C2 + seg * 8, rbh + (size_t)r * HH + CH2 + seg * 8);
                else
                    cp_async16(HsL + bo + r * RS_C2 + seg * 8, rbl + (size_t)r * HH + CH2 + seg * 8);
            }
            CP_COMMIT();
        }

        for (int ci = 0; ci < NCH2; ci++) {
            CP_WAIT(1);
            __syncthreads();

            int bo = (ci & 1) * 64 * RS_C2;
            const __nv_bfloat16* hH = HsH + bo;
            const __nv_bfloat16* hL = HsL + bo;
#pragma unroll
            for (int kk = 0; kk < 64; kk += 16) {
                int kl = kks + kk;               // k within chunk
                int kw = ci * CH2 + kl;          // global k for resident W
                uint32_t ah0 = *(uint32_t*)&hH[r0 * RS_C2 + kl + 2 * tg];
                uint32_t ah1 = *(uint32_t*)&hH[(r0 + 8) * RS_C2 + kl + 2 * tg];
                uint32_t ah2 = *(uint32_t*)&hH[r0 * RS_C2 + kl + 2 * tg + 8];
                uint32_t ah3 = *(uint32_t*)&hH[(r0 + 8) * RS_C2 + kl + 2 * tg + 8];
                uint32_t al0 = *(uint32_t*)&hL[r0 * RS_C2 + kl + 2 * tg];
                uint32_t al1 = *(uint32_t*)&hL[(r0 + 8) * RS_C2 + kl + 2 * tg];
                uint32_t al2 = *(uint32_t*)&hL[r0 * RS_C2 + kl + 2 * tg + 8];
                uint32_t al3 = *(uint32_t*)&hL[(r0 + 8) * RS_C2 + kl + 2 * tg + 8];
#pragma unroll
                for (int nf = 0; nf < 4; nf++) {
                    int n = nf * 8 + gq;
                    uint32_t bh0 = *(uint32_t*)&Wh[n * RS_W2 + kw + 2 * tg];
                    uint32_t bh1 = *(uint32_t*)&Wh[n * RS_W2 + kw + 2 * tg + 8];
                    uint32_t bl0 = *(uint32_t*)&Wl[n * RS_W2 + kw + 2 * tg];
                    uint32_t bl1 = *(uint32_t*)&Wl[n * RS_W2 + kw + 2 * tg + 8];
                    mma16816(acc[nf], ah0, ah1, ah2, ah3, bh0, bh1);
                    mma16816(acc[nf], al0, al1, al2, al3, bh0, bh1);
                    mma16816(acc[nf], ah0, ah1, ah2, ah3, bl0, bl1);
                }
            }
            __syncthreads();

            if (ci + 2 < NCH2) {
                int kc = (ci + 2) * CH2;
                int bo2 = ((ci + 2) & 1) * 64 * RS_C2;
#pragma unroll
                for (int s = tid; s < 2048; s += 256) {
                    int plane = s >> 10, r = (s >> 4) & 63, seg = s & 15;
                    if (plane == 0)
                        cp_async16(HsH + bo2 + r * RS_C2 + seg * 8, rbh + (size_t)r * HH + kc + seg * 8);
                    else
                        cp_async16(HsL + bo2 + r * RS_C2 + seg * 8, rbl + (size_t)r * HH + kc + seg * 8);
                }
            }
            CP_COMMIT();   // always commit (possibly empty) to keep group count uniform
        }

        // k-group reduction: kg=1 dumps partials, kg=0 combines into Gs
        if (kg == 1) {
#pragma unroll
            for (int nf = 0; nf < 4; nf++) {
                int col = nf * 8 + 2 * tg;
                PS[r0 * RS_G + col] = acc[nf][0];
                PS[r0 * RS_G + col + 1] = acc[nf][1];
                PS[(r0 + 8) * RS_G + col] = acc[nf][2];
                PS[(r0 + 8) * RS_G + col + 1] = acc[nf][3];
            }
        }
        __syncthreads();
        if (kg == 0) {
#pragma unroll
            for (int nf = 0; nf < 4; nf++) {
                int col = nf * 8 + 2 * tg;
                Gs[r0 * RS_G + col] = acc[nf][0] + PS[r0 * RS_G + col];
                Gs[r0 * RS_G + col + 1] = acc[nf][1] + PS[r0 * RS_G + col + 1];
                Gs[(r0 + 8) * RS_G + col] = acc[nf][2] + PS[(r0 + 8) * RS_G + col];
                Gs[(r0 + 8) * RS_G + col + 1] = acc[nf][3] + PS[(r0 + 8) * RS_G + col + 1];
            }
        }
        __syncthreads();

        // cell update: 64 batches x 8 cols (xp from SMEM stage)
#pragma unroll
        for (int e = tid; e < 512; e += 256) {
            int b = e >> 3, i = e & 7;
            float gi = Gs[b * RS_G + i]      + XPs[b * RS_G + i];
            float gf = Gs[b * RS_G + 8 + i]  + XPs[b * RS_G + 8 + i];
            float gg = Gs[b * RS_G + 16 + i] + XPs[b * RS_G + 16 + i];
            float go = Gs[b * RS_G + 24 + i] + XPs[b * RS_G + 24 + i];
            float si = sigmoid_f(gi);
            float sf = sigmoid_f(gf);
            float sg = tanh_f(gg);
            float so = sigmoid_f(go);
            float c = sf * Cs[e] + si * sg;
            Cs[e] = c;
            float h = so * tanh_f(c);
            __nv_bfloat16 hi, lo;
            split_bf16(h, hi, lo);
            size_t po = (size_t)b * HH + j0 + i;
            wbh[po] = hi;
            wbl[po] = lo;
            size_t so2 = ((size_t)t * BB + b) * HH + j0 + i;
            g_hseq_h[so2] = hi;
            g_hseq_l[so2] = lo;
        }
        __syncthreads();

        // publish completion of step t (release)
        if (tid == 0) {
            __threadfence();
            g_flags[blockIdx.x * 32] = (unsigned)(t + 1);
        }
    }
}

// ---------------- final linear ----------------
__global__ void final_kernel(const float* __restrict__ w_lin,
                             const float* __restrict__ b_lin,
                             float* __restrict__ out) {
    int b = blockIdx.x;
    __shared__ float red[256];
    float s = 0.f;
    size_t base = ((size_t)(TT - 1) * BB + b) * HH;
    for (int i = threadIdx.x; i < HH; i += 256) {
        float h = __bfloat162float(g_hseq_h[base + i]) + __bfloat162float(g_hseq_l[base + i]);
        s += h * w_lin[i];
    }
    red[threadIdx.x] = s;
    __syncthreads();
    for (int st = 128; st > 0; st >>= 1) {
        if (threadIdx.x < st) red[threadIdx.x] += red[threadIdx.x + st];
        __syncthreads();
    }
    if (threadIdx.x == 0) out[b] = red[0] + b_lin[0];
}

// ---------------- launch ----------------
extern "C" void kernel_launch(void* const* d_in, const int* in_sizes, int n_in,
                              void* d_out, int out_size) {
    const float* x     = (const float*)d_in[0];
    const float* w_ih0 = (const float*)d_in[1];
    const float* w_hh0 = (const float*)d_in[2];
    const float* b_ih0 = (const float*)d_in[3];
    const float* b_hh0 = (const float*)d_in[4];
    const float* w_ih1 = (const float*)d_in[5];
    const float* w_hh1 = (const float*)d_in[6];
    const float* b_ih1 = (const float*)d_in[7];
    const float* b_hh1 = (const float*)d_in[8];
    const float* w_lin = (const float*)d_in[9];
    const float* b_lin = (const float*)d_in[10];
    float* out = (float*)d_out;

    cudaFuncSetAttribute(recur_kernel, cudaFuncAttributeMaxDynamicSharedMemorySize,
                         SMEM_RECUR);

    // layer 0
    prep_kernel<<<256, 256>>>();
    convert_x_kernel<<<2048, 256>>>(x);
    convert_wih_kernel<<<1024, 256>>>(w_ih0, GG * DD);
    gemm_kernel<<<dim3(64, 512), 256>>>(0, DD, b_ih0, b_hh0);
    recur_kernel<<<NCTA, 256, SMEM_RECUR>>>(w_hh0);

    // layer 1
    prep_kernel<<<256, 256>>>();
    convert_wih_kernel<<<4096, 256>>>(w_ih1, GG * HH);
    gemm_kernel<<<dim3(64, 512), 256>>>(1, HH, b_ih1, b_hh1);
    recur_kernel<<<NCTA, 256, SMEM_RECUR>>>(w_hh1);

    // output head
    final_kernel<<<64, 256>>>(w_lin, b_lin, out);
}

// round 15
// speedup vs baseline: 1.4163x; 1.0282x over previous
#include <cuda_runtime.h>
#include <cuda_bf16.h>
#include <cstdint>

#define BB 64      // batch
#define TT 512     // timesteps
#define DD 256     // input dim
#define HH 1024    // hidden
#define GG 4096    // 4*H

// ---------------- scratch (device-global; no allocs allowed) ----------------
__device__ __align__(16) __nv_bfloat16 g_A0h[(size_t)TT * BB * DD];   // x hi plane [t*B+b][D]
__device__ __align__(16) __nv_bfloat16 g_A0l[(size_t)TT * BB * DD];   // x lo plane
__device__ __align__(16) __nv_bfloat16 g_wbh[(size_t)GG * HH];        // w_ih hi
__device__ __align__(16) __nv_bfloat16 g_wbl[(size_t)GG * HH];        // w_ih lo
__device__ __align__(16) float         g_xp[(size_t)TT * BB * GG];    // projections + biases
__device__ __align__(16) __nv_bfloat16 g_hseq_h[(size_t)TT * BB * HH];
__device__ __align__(16) __nv_bfloat16 g_hseq_l[(size_t)TT * BB * HH];
__device__ __align__(16) __nv_bfloat16 g_hbuf_h[2][BB * HH];
__device__ __align__(16) __nv_bfloat16 g_hbuf_l[2][BB * HH];
__device__ volatile unsigned g_flags[128 * 32];   // per-CTA step flags, 128B stride

#define NCTA 128     // recurrence CTAs (all resident, 1/SM)
#define NT   512     // recurrence threads per CTA (16 warps = 4/SMSP)

// SMEM strides (word stride mod 32 == 4 -> conflict-free quad access)
#define RS_C 72      // gemm chunk row stride (bf16)
#define RS_C2 136    // recur h-chunk row stride (bf16): 68 words, 68%32=4
#define RS_W2 1032   // resident W row stride (bf16): 516 words, 516%32=4
#define RS_G 36      // gate row stride (fp32)
#define CH2  128     // recur k-chunk width
#define NCH2 8       // 1024/128 chunks

// recurrence SMEM layout (bytes)
#define OFF_WH 0                               // 2 planes * 32*RS_W2*2 = 132096
#define OFF_HH 132096                          // 2 bufs*64*RS_C2*2 = 34816
#define OFF_HL 166912                          // -> 201728
#define OFF_PS 201728                          // 3 sets * 64*RS_G*4 = 27648 (set0 doubles as Gs)
#define OFF_CS 229376                          // 512*4 = 2048
#define SMEM_RECUR 231424

// ---------------- helpers ----------------
__device__ __forceinline__ void mma16816(float* c, uint32_t a0, uint32_t a1,
                                         uint32_t a2, uint32_t a3,
                                         uint32_t b0, uint32_t b1) {
    asm volatile(
        "mma.sync.aligned.m16n8k16.row.col.f32.bf16.bf16.f32 "
        "{%0,%1,%2,%3}, {%4,%5,%6,%7}, {%8,%9}, {%0,%1,%2,%3};"
        : "+f"(c[0]), "+f"(c[1]), "+f"(c[2]), "+f"(c[3])
        : "r"(a0), "r"(a1), "r"(a2), "r"(a3), "r"(b0), "r"(b1));
}
__device__ __forceinline__ void cp_async16(void* s, const void* g) {
    uint32_t sa = (uint32_t)__cvta_generic_to_shared(s);
    asm volatile("cp.async.cg.shared.global [%0], [%1], 16;\n" ::"r"(sa), "l"(g));
}
#define CP_COMMIT() asm volatile("cp.async.commit_group;\n")
#define CP_WAIT(N)  asm volatile("cp.async.wait_group %0;\n" ::"n"(N))

__device__ __forceinline__ float sigmoid_f(float x) { return 1.f / (1.f + __expf(-x)); }
__device__ __forceinline__ float tanh_f(float x) { return 2.f / (1.f + __expf(-2.f * x)) - 1.f; }

__device__ __forceinline__ void split_bf16(float v, __nv_bfloat16& hi, __nv_bfloat16& lo) {
    hi = __float2bfloat16(v);
    lo = __float2bfloat16(v - __bfloat162float(hi));
}

// ---------------- prep: zero flags + h buffers ----------------
__global__ void prep_kernel() {
    int idx = blockIdx.x * blockDim.x + threadIdx.x;
    int nflag = 128 * 32;
    int nh = 2 * BB * HH;
    int total = nflag + 2 * nh;
    for (int i = idx; i < total; i += gridDim.x * blockDim.x) {
        if (i < nflag) g_flags[i] = 0u;
        else if (i < nflag + nh) ((__nv_bfloat16*)g_hbuf_h)[i - nflag] = __float2bfloat16(0.f);
        else ((__nv_bfloat16*)g_hbuf_l)[i - nflag - nh] = __float2bfloat16(0.f);
    }
}

// x[B][T][D] fp32 -> split planes [t*B+b][D]
__global__ void convert_x_kernel(const float* __restrict__ x) {
    size_t total = (size_t)BB * TT * DD;
    for (size_t i = (size_t)blockIdx.x * blockDim.x + threadIdx.x; i < total;
         i += (size_t)gridDim.x * blockDim.x) {
        int b = (int)(i / (TT * DD));
        int r = (int)(i % (TT * DD));
        int t = r / DD, d = r % DD;
        __nv_bfloat16 hi, lo;
        split_bf16(x[i], hi, lo);
        size_t o = ((size_t)t * BB + b) * DD + d;
        g_A0h[o] = hi;
        g_A0l[o] = lo;
    }
}

__global__ void convert_wih_kernel(const float* __restrict__ w, int n) {
    for (int i = blockIdx.x * blockDim.x + threadIdx.x; i < n; i += gridDim.x * blockDim.x) {
        __nv_bfloat16 hi, lo;
        split_bf16(w[i], hi, lo);
        g_wbh[i] = hi;
        g_wbl[i] = lo;
    }
}

// ---------------- projection GEMM (bf16x3): C = A.Wt + b1 + b2 ----------------
__global__ __launch_bounds__(256) void gemm_kernel(int layer, int K,
                                                   const float* __restrict__ bias1,
                                                   const float* __restrict__ bias2) {
    const __nv_bfloat16* Ah = (layer == 0) ? g_A0h : g_hseq_h;
    const __nv_bfloat16* Al = (layer == 0) ? g_A0l : g_hseq_l;
    __shared__ __nv_bfloat16 AsH[64][RS_C], AsL[64][RS_C];
    __shared__ __nv_bfloat16 BsH[64][RS_C], BsL[64][RS_C];

    int tid = threadIdx.x;
    int m0 = blockIdx.y * 64, n0 = blockIdx.x * 64;
    int lane = tid & 31, wid = tid >> 5;
    int gq = lane >> 2, tg = lane & 3;
    int mrow = (wid & 3) * 16;
    int nq = (wid >> 2) * 32;

    float acc[4][4];
#pragma unroll
    for (int a = 0; a < 4; a++)
#pragma unroll
        for (int b = 0; b < 4; b++) acc[a][b] = 0.f;

    for (int kt = 0; kt < K; kt += 64) {
#pragma unroll
        for (int f4 = tid; f4 < 512; f4 += 256) {
            int row = f4 >> 3, c = f4 & 7;
            *((float4*)&AsH[row][c * 8]) = *(const float4*)(Ah + (size_t)(m0 + row) * K + kt + c * 8);
            *((float4*)&AsL[row][c * 8]) = *(const float4*)(Al + (size_t)(m0 + row) * K + kt + c * 8);
            *((float4*)&BsH[row][c * 8]) = *(const float4*)(g_wbh + (size_t)(n0 + row) * K + kt + c * 8);
            *((float4*)&BsL[row][c * 8]) = *(const float4*)(g_wbl + (size_t)(n0 + row) * K + kt + c * 8);
        }
        __syncthreads();
#pragma unroll
        for (int kk = 0; kk < 64; kk += 16) {
            uint32_t ah0 = *(uint32_t*)&AsH[mrow + gq][kk + 2 * tg];
            uint32_t ah1 = *(uint32_t*)&AsH[mrow + gq + 8][kk + 2 * tg];
            uint32_t ah2 = *(uint32_t*)&AsH[mrow + gq][kk + 2 * tg + 8];
            uint32_t ah3 = *(uint32_t*)&AsH[mrow + gq + 8][kk + 2 * tg + 8];
            uint32_t al0 = *(uint32_t*)&AsL[mrow + gq][kk + 2 * tg];
            uint32_t al1 = *(uint32_t*)&AsL[mrow + gq + 8][kk + 2 * tg];
            uint32_t al2 = *(uint32_t*)&AsL[mrow + gq][kk + 2 * tg + 8];
            uint32_t al3 = *(uint32_t*)&AsL[mrow + gq + 8][kk + 2 * tg + 8];
#pragma unroll
            for (int nf = 0; nf < 4; nf++) {
                int n = nq + nf * 8 + gq;
                uint32_t bh0 = *(uint32_t*)&BsH[n][kk + 2 * tg];
                uint32_t bh1 = *(uint32_t*)&BsH[n][kk + 2 * tg + 8];
                uint32_t bl0 = *(uint32_t*)&BsL[n][kk + 2 * tg];
                uint32_t bl1 = *(uint32_t*)&BsL[n][kk + 2 * tg + 8];
                mma16816(acc[nf], ah0, ah1, ah2, ah3, bh0, bh1);
                mma16816(acc[nf], al0, al1, al2, al3, bh0, bh1);
                mma16816(acc[nf], ah0, ah1, ah2, ah3, bl0, bl1);
            }
        }
        __syncthreads();
    }

#pragma unroll
    for (int nf = 0; nf < 4; nf++) {
        int col = n0 + nq + nf * 8 + 2 * tg;
        float bs0 = bias1[col] + bias2[col];
        float bs1 = bias1[col + 1] + bias2[col + 1];
        int r0 = m0 + mrow + gq;
        g_xp[(size_t)r0 * GG + col] = acc[nf][0] + bs0;
        g_xp[(size_t)r0 * GG + col + 1] = acc[nf][1] + bs1;
        g_xp[(size_t)(r0 + 8) * GG + col] = acc[nf][2] + bs0;
        g_xp[(size_t)(r0 + 8) * GG + col + 1] = acc[nf][3] + bs1;
    }
}

// ---------------- persistent recurrence (bf16x3), 128 CTAs x 512 thr ----------------
// CTA owns 8 h-cols (32 gate rows). Both W planes SMEM-resident. h hi/lo
// streamed per 128-wide chunk (cp.async, double buffered, both pre-issued).
// 16 warps = 4 m-warps x 4 k-groups; warp tile m16 x n32, k-slice 32/chunk.
// 3 partial sets in SMEM; set 0 doubles as final gate buffer.
// xp(t) prefetched into registers right after the step barrier.
__global__ __launch_bounds__(NT, 1) void recur_kernel(const float* __restrict__ w_hh) {
    extern __shared__ unsigned char smem[];
    __nv_bfloat16* Wh = (__nv_bfloat16*)(smem + OFF_WH);
    __nv_bfloat16* Wl = (__nv_bfloat16*)(smem + OFF_WH + 66048);
    __nv_bfloat16* HsH = (__nv_bfloat16*)(smem + OFF_HH);   // 2 bufs of 64*RS_C2
    __nv_bfloat16* HsL = (__nv_bfloat16*)(smem + OFF_HL);
    float* PS = (float*)(smem + OFF_PS);                    // 3 sets; set0 = Gs
    float* Cs = (float*)(smem + OFF_CS);

    int tid = threadIdx.x;
    int j0 = blockIdx.x * 8;

    // Preload resident W slice (both planes), split from fp32
    for (int idx = tid; idx < 32 * 1024; idx += NT) {
        int r = idx >> 10, k = idx & 1023;
        int q = r >> 3, i = r & 7;
        float v = w_hh[(size_t)(q * HH + j0 + i) * HH + k];
        __nv_bfloat16 hi, lo;
        split_bf16(v, hi, lo);
        Wh[r * RS_W2 + k] = hi;
        Wl[r * RS_W2 + k] = lo;
    }
    if (tid < 512) Cs[tid] = 0.f;
    __syncthreads();

    int lane = tid & 31, wid = tid >> 5;
    int gq = lane >> 2, tg = lane & 3;
    int mw = wid & 3;            // m-warp: rows mw*16..mw*16+15
    int kg = wid >> 2;           // k-group 0..3: k-slice kg*32 within chunk
    int r0 = mw * 16 + gq;
    int kks = kg * 32;
    // cell-update ownership: thread e = tid (512 elems), b = e>>3, i = e&7
    int ub = tid >> 3, ui = tid & 7;

    for (int t = 0; t < TT; t++) {
        // step barrier: wait for all CTAs to have finished step t-1
        if (t > 0) {
            if (tid < NCTA) {
                while (g_flags[tid * 32] < (unsigned)t) {}
            }
            __syncthreads();
        }

        const __nv_bfloat16* rbh = g_hbuf_h[(t + 1) & 1];
        const __nv_bfloat16* rbl = g_hbuf_l[(t + 1) & 1];
        __nv_bfloat16* wbh = g_hbuf_h[t & 1];
        __nv_bfloat16* wbl = g_hbuf_l[t & 1];
        const float* xpt = g_xp + (size_t)t * BB * GG;

        // prefetch this thread's xp gates into registers (used ~8 chunks later)
        float xg0 = __ldg(xpt + (size_t)ub * GG + j0 + ui);
        float xg1 = __ldg(xpt + (size_t)ub * GG + HH + j0 + ui);
        float xg2 = __ldg(xpt + (size_t)ub * GG + 2 * HH + j0 + ui);
        float xg3 = __ldg(xpt + (size_t)ub * GG + 3 * HH + j0 + ui);

        float acc[4][4];
#pragma unroll
        for (int a = 0; a < 4; a++)
#pragma unroll
            for (int b = 0; b < 4; b++) acc[a][b] = 0.f;

        // pre-issue chunk 0 and chunk 1
        {
#pragma unroll
            for (int s = tid; s < 2048; s += NT) {
                int plane = s >> 10, r = (s >> 4) & 63, seg = s & 15;
                if (plane == 0)
                    cp_async16(HsH + r * RS_C2 + seg * 8, rbh + (size_t)r * HH + seg * 8);
                else
                    cp_async16(HsL + r * RS_C2 + seg * 8, rbl + (size_t)r * HH + seg * 8);
            }
            CP_COMMIT();
            int bo = 64 * RS_C2;
#pragma unroll
            for (int s = tid; s < 2048; s += NT) {
                int plane = s >> 10, r = (s >> 4) & 63, seg = s & 15;
                if (plane == 0)
                    cp_async16(HsH + bo + r * RS_C2 + seg * 8, rbh + (size_t)r * HH + CH2 + seg * 8);
                else
                    cp_async16(HsL + bo + r * RS_C2 + seg * 8, rbl + (size_t)r * HH + CH2 + seg * 8);
            }
            CP_COMMIT();
        }

        for (int ci = 0; ci < NCH2; ci++) {
            CP_WAIT(1);
            __syncthreads();

            int bo = (ci & 1) * 64 * RS_C2;
            const __nv_bfloat16* hH = HsH + bo;
            const __nv_bfloat16* hL = HsL + bo;
#pragma unroll
            for (int kk = 0; kk < 32; kk += 16) {
                int kl = kks + kk;               // k within chunk
                int kw = ci * CH2 + kl;          // global k for resident W
                uint32_t ah0 = *(uint32_t*)&hH[r0 * RS_C2 + kl + 2 * tg];
                uint32_t ah1 = *(uint32_t*)&hH[(r0 + 8) * RS_C2 + kl + 2 * tg];
                uint32_t ah2 = *(uint32_t*)&hH[r0 * RS_C2 + kl + 2 * tg + 8];
                uint32_t ah3 = *(uint32_t*)&hH[(r0 + 8) * RS_C2 + kl + 2 * tg + 8];
                uint32_t al0 = *(uint32_t*)&hL[r0 * RS_C2 + kl + 2 * tg];
                uint32_t al1 = *(uint32_t*)&hL[(r0 + 8) * RS_C2 + kl + 2 * tg];
                uint32_t al2 = *(uint32_t*)&hL[r0 * RS_C2 + kl + 2 * tg + 8];
                uint32_t al3 = *(uint32_t*)&hL[(r0 + 8) * RS_C2 + kl + 2 * tg + 8];
#pragma unroll
                for (int nf = 0; nf < 4; nf++) {
                    int n = nf * 8 + gq;
                    uint32_t bh0 = *(uint32_t*)&Wh[n * RS_W2 + kw + 2 * tg];
                    uint32_t bh1 = *(uint32_t*)&Wh[n * RS_W2 + kw + 2 * tg + 8];
                    uint32_t bl0 = *(uint32_t*)&Wl[n * RS_W2 + kw + 2 * tg];
                    uint32_t bl1 = *(uint32_t*)&Wl[n * RS_W2 + kw + 2 * tg + 8];
                    mma16816(acc[nf], ah0, ah1, ah2, ah3, bh0, bh1);
                    mma16816(acc[nf], al0, al1, al2, al3, bh0, bh1);
                    mma16816(acc[nf], ah0, ah1, ah2, ah3, bl0, bl1);
                }
            }
            __syncthreads();

            if (ci + 2 < NCH2) {
                int kc = (ci + 2) * CH2;
                int bo2 = ((ci + 2) & 1) * 64 * RS_C2;
#pragma unroll
                for (int s = tid; s < 2048; s += NT) {
                    int plane = s >> 10, r = (s >> 4) & 63, seg = s & 15;
                    if (plane == 0)
                        cp_async16(HsH + bo2 + r * RS_C2 + seg * 8, rbh + (size_t)r * HH + kc + seg * 8);
                    else
                        cp_async16(HsL + bo2 + r * RS_C2 + seg * 8, rbl + (size_t)r * HH + kc + seg * 8);
                }
            }
            CP_COMMIT();   // always commit (possibly empty) to keep group count uniform
        }

        // k-group reduction: kg=1,2,3 dump partials, kg=0 combines into PS set0
        if (kg != 0) {
            float* P = PS + (kg - 1) * 64 * RS_G;
#pragma unroll
            for (int nf = 0; nf < 4; nf++) {
                int col = nf * 8 + 2 * tg;
                P[r0 * RS_G + col] = acc[nf][0];
                P[r0 * RS_G + col + 1] = acc[nf][1];
                P[(r0 + 8) * RS_G + col] = acc[nf][2];
                P[(r0 + 8) * RS_G + col + 1] = acc[nf][3];
            }
        }
        __syncthreads();
        if (kg == 0) {
            float* P1 = PS + 0 * 64 * RS_G;   // also the output (Gs)
            float* P2 = PS + 1 * 64 * RS_G;
            float* P3 = PS + 2 * 64 * RS_G;
#pragma unroll
            for (int nf = 0; nf < 4; nf++) {
                int col = nf * 8 + 2 * tg;
                int a0 = r0 * RS_G + col, a1 = r0 * RS_G + col + 1;
                int a2 = (r0 + 8) * RS_G + col, a3 = (r0 + 8) * RS_G + col + 1;
                P1[a0] = acc[nf][0] + P1[a0] + P2[a0] + P3[a0];
                P1[a1] = acc[nf][1] + P1[a1] + P2[a1] + P3[a1];
                P1[a2] = acc[nf][2] + P1[a2] + P2[a2] + P3[a2];
                P1[a3] = acc[nf][3] + P1[a3] + P2[a3] + P3[a3];
            }
        }
        __syncthreads();

        // cell update: 512 elems, one per thread (Gs = PS set0)
        {
            const float* Gs = PS;
            float gi = Gs[ub * RS_G + ui]      + xg0;
            float gf = Gs[ub * RS_G + 8 + ui]  + xg1;
            float gg = Gs[ub * RS_G + 16 + ui] + xg2;
            float go = Gs[ub * RS_G + 24 + ui] + xg3;
            float si = sigmoid_f(gi);
            float sf = sigmoid_f(gf);
            float sg = tanh_f(gg);
            float so = sigmoid_f(go);
            float c = sf * Cs[tid] + si * sg;
            Cs[tid] = c;
            float h = so * tanh_f(c);
            __nv_bfloat16 hi, lo;
            split_bf16(h, hi, lo);
            size_t po = (size_t)ub * HH + j0 + ui;
            wbh[po] = hi;
            wbl[po] = lo;
            size_t so2 = ((size_t)t * BB + ub) * HH + j0 + ui;
            g_hseq_h[so2] = hi;
            g_hseq_l[so2] = lo;
        }
        __syncthreads();

        // publish completion of step t (release)
        if (tid == 0) {
            __threadfence();
            g_flags[blockIdx.x * 32] = (unsigned)(t + 1);
        }
    }
}

// ---------------- final linear ----------------
__global__ void final_kernel(const float* __restrict__ w_lin,
                             const float* __restrict__ b_lin,
                             float* __restrict__ out) {
    int b = blockIdx.x;
    __shared__ float red[256];
    float s = 0.f;
    size_t base = ((size_t)(TT - 1) * BB + b) * HH;
    for (int i = threadIdx.x; i < HH; i += 256) {
        float h = __bfloat162float(g_hseq_h[base + i]) + __bfloat162float(g_hseq_l[base + i]);
        s += h * w_lin[i];
    }
    red[threadIdx.x] = s;
    __syncthreads();
    for (int st = 128; st > 0; st >>= 1) {
        if (threadIdx.x < st) red[threadIdx.x] += red[threadIdx.x + st];
        __syncthreads();
    }
    if (threadIdx.x == 0) out[b] = red[0] + b_lin[0];
}

// ---------------- launch ----------------
extern "C" void kernel_launch(void* const* d_in, const int* in_sizes, int n_in,
                              void* d_out, int out_size) {
    const float* x     = (const float*)d_in[0];
    const float* w_ih0 = (const float*)d_in[1];
    const float* w_hh0 = (const float*)d_in[2];
    const float* b_ih0 = (const float*)d_in[3];
    const float* b_hh0 = (const float*)d_in[4];
    const float* w_ih1 = (const float*)d_in[5];
    const float* w_hh1 = (const float*)d_in[6];
    const float* b_ih1 = (const float*)d_in[7];
    const float* b_hh1 = (const float*)d_in[8];
    const float* w_lin = (const float*)d_in[9];
    const float* b_lin = (const float*)d_in[10];
    float* out = (float*)d_out;

    cudaFuncSetAttribute(recur_kernel, cudaFuncAttributeMaxDynamicSharedMemorySize,
                         SMEM_RECUR);

    // layer 0
    prep_kernel<<<256, 256>>>();
    convert_x_kernel<<<2048, 256>>>(x);
    convert_wih_kernel<<<1024, 256>>>(w_ih0, GG * DD);
    gemm_kernel<<<dim3(64, 512), 256>>>(0, DD, b_ih0, b_hh0);
    recur_kernel<<<NCTA, NT, SMEM_RECUR>>>(w_hh0);

    // layer 1
    prep_kernel<<<256, 256>>>();
    convert_wih_kernel<<<4096, 256>>>(w_ih1, GG * HH);
    gemm_kernel<<<dim3(64, 512), 256>>>(1, HH, b_ih1, b_hh1);
    recur_kernel<<<NCTA, NT, SMEM_RECUR>>>(w_hh1);

    // output head
    final_kernel<<<64, 256>>>(w_lin, b_lin, out);
}

// round 16
// speedup vs baseline: 1.7553x; 1.2394x over previous
#include <cuda_runtime.h>
#include <cuda_fp16.h>
#include <cstdint>

#define BB 64      // batch
#define TT 512     // timesteps
#define DD 256     // input dim
#define HH 1024    // hidden
#define GG 4096    // 4*H

// ---------------- scratch (device-global; no allocs allowed) ----------------
__device__ __align__(16) __half g_A0h[(size_t)TT * BB * DD];   // x hi plane [t*B+b][D]
__device__ __align__(16) __half g_A0l[(size_t)TT * BB * DD];   // x lo plane
__device__ __align__(16) __half g_wbh[(size_t)GG * HH];        // w_ih hi
__device__ __align__(16) __half g_wbl[(size_t)GG * HH];        // w_ih lo
__device__ __align__(16) float  g_xp[(size_t)TT * BB * GG];    // projections + biases
__device__ __align__(16) __half g_hseq_h[(size_t)TT * BB * HH];
__device__ __align__(16) __half g_hseq_l[(size_t)TT * BB * HH];
__device__ __align__(16) __half g_hbuf[2][BB * HH];            // single-plane h stream
__device__ volatile unsigned g_flags[128 * 32];   // per-CTA step flags, 128B stride

#define NCTA 128     // recurrence CTAs (all resident, 1/SM)
#define NT   256     // recurrence threads per CTA (8 warps)

// SMEM strides (word stride mod 32 == 4 -> conflict-free quad access)
#define RS_C 72      // gemm chunk row stride (fp16)
#define RS_C2 136    // recur h-chunk row stride (fp16): 68 words, 68%32=4
#define RS_W2 1032   // resident W row stride (fp16): 516 words, 516%32=4
#define RS_G 36      // gate row stride (fp32)
#define CH2  128     // recur k-chunk width
#define NCH2 8       // 1024/128 chunks

// recurrence SMEM layout (bytes)
#define OFF_WH 0                               // 2 planes * 32*RS_W2*2 = 132096
#define OFF_HS 132096                          // 4 bufs * 64*RS_C2*2 = 69632
#define OFF_PS 201728                          // 3 sets * 64*RS_G*4 = 27648 (set0 = Gs)
#define OFF_CS 229376                          // 512*4 = 2048
#define SMEM_RECUR 231424

// ---------------- helpers ----------------
__device__ __forceinline__ void mma16816(float* c, uint32_t a0, uint32_t a1,
                                         uint32_t a2, uint32_t a3,
                                         uint32_t b0, uint32_t b1) {
    asm volatile(
        "mma.sync.aligned.m16n8k16.row.col.f32.f16.f16.f32 "
        "{%0,%1,%2,%3}, {%4,%5,%6,%7}, {%8,%9}, {%0,%1,%2,%3};"
        : "+f"(c[0]), "+f"(c[1]), "+f"(c[2]), "+f"(c[3])
        : "r"(a0), "r"(a1), "r"(a2), "r"(a3), "r"(b0), "r"(b1));
}
__device__ __forceinline__ void cp_async16(void* s, const void* g) {
    uint32_t sa = (uint32_t)__cvta_generic_to_shared(s);
    asm volatile("cp.async.cg.shared.global [%0], [%1], 16;\n" ::"r"(sa), "l"(g));
}
#define CP_COMMIT() asm volatile("cp.async.commit_group;\n")
#define CP_WAIT(N)  asm volatile("cp.async.wait_group %0;\n" ::"n"(N))

__device__ __forceinline__ float sigmoid_f(float x) { return 1.f / (1.f + __expf(-x)); }
__device__ __forceinline__ float tanh_f(float x) { return 2.f / (1.f + __expf(-2.f * x)) - 1.f; }

__device__ __forceinline__ void split_f16(float v, __half& hi, __half& lo) {
    hi = __float2half(v);
    lo = __float2half(v - __half2float(hi));
}

// ---------------- prep: zero flags + h buffers ----------------
__global__ void prep_kernel() {
    int idx = blockIdx.x * blockDim.x + threadIdx.x;
    int nflag = 128 * 32;
    int nh = 2 * BB * HH;     // both step buffers, single plane
    int total = nflag + nh;
    for (int i = idx; i < total; i += gridDim.x * blockDim.x) {
        if (i < nflag) g_flags[i] = 0u;
        else ((__half*)g_hbuf)[i - nflag] = __float2half(0.f);
    }
}

// x[B][T][D] fp32 -> split planes [t*B+b][D]
__global__ void convert_x_kernel(const float* __restrict__ x) {
    size_t total = (size_t)BB * TT * DD;
    for (size_t i = (size_t)blockIdx.x * blockDim.x + threadIdx.x; i < total;
         i += (size_t)gridDim.x * blockDim.x) {
        int b = (int)(i / (TT * DD));
        int r = (int)(i % (TT * DD));
        int t = r / DD, d = r % DD;
        __half hi, lo;
        split_f16(x[i], hi, lo);
        size_t o = ((size_t)t * BB + b) * DD + d;
        g_A0h[o] = hi;
        g_A0l[o] = lo;
    }
}

__global__ void convert_wih_kernel(const float* __restrict__ w, int n) {
    for (int i = blockIdx.x * blockDim.x + threadIdx.x; i < n; i += gridDim.x * blockDim.x) {
        __half hi, lo;
        split_f16(w[i], hi, lo);
        g_wbh[i] = hi;
        g_wbl[i] = lo;
    }
}

// ---------------- projection GEMM (fp16x3): C = A.Wt + b1 + b2 ----------------
__global__ __launch_bounds__(256) void gemm_kernel(int layer, int K,
                                                   const float* __restrict__ bias1,
                                                   const float* __restrict__ bias2) {
    const __half* Ah = (layer == 0) ? g_A0h : g_hseq_h;
    const __half* Al = (layer == 0) ? g_A0l : g_hseq_l;
    __shared__ __half AsH[64][RS_C], AsL[64][RS_C];
    __shared__ __half BsH[64][RS_C], BsL[64][RS_C];

    int tid = threadIdx.x;
    int m0 = blockIdx.y * 64, n0 = blockIdx.x * 64;
    int lane = tid & 31, wid = tid >> 5;
    int gq = lane >> 2, tg = lane & 3;
    int mrow = (wid & 3) * 16;
    int nq = (wid >> 2) * 32;

    float acc[4][4];
#pragma unroll
    for (int a = 0; a < 4; a++)
#pragma unroll
        for (int b = 0; b < 4; b++) acc[a][b] = 0.f;

    for (int kt = 0; kt < K; kt += 64) {
#pragma unroll
        for (int f4 = tid; f4 < 512; f4 += 256) {
            int row = f4 >> 3, c = f4 & 7;
            *((float4*)&AsH[row][c * 8]) = *(const float4*)(Ah + (size_t)(m0 + row) * K + kt + c * 8);
            *((float4*)&AsL[row][c * 8]) = *(const float4*)(Al + (size_t)(m0 + row) * K + kt + c * 8);
            *((float4*)&BsH[row][c * 8]) = *(const float4*)(g_wbh + (size_t)(n0 + row) * K + kt + c * 8);
            *((float4*)&BsL[row][c * 8]) = *(const float4*)(g_wbl + (size_t)(n0 + row) * K + kt + c * 8);
        }
        __syncthreads();
#pragma unroll
        for (int kk = 0; kk < 64; kk += 16) {
            uint32_t ah0 = *(uint32_t*)&AsH[mrow + gq][kk + 2 * tg];
            uint32_t ah1 = *(uint32_t*)&AsH[mrow + gq + 8][kk + 2 * tg];
            uint32_t ah2 = *(uint32_t*)&AsH[mrow + gq][kk + 2 * tg + 8];
            uint32_t ah3 = *(uint32_t*)&AsH[mrow + gq + 8][kk + 2 * tg + 8];
            uint32_t al0 = *(uint32_t*)&AsL[mrow + gq][kk + 2 * tg];
            uint32_t al1 = *(uint32_t*)&AsL[mrow + gq + 8][kk + 2 * tg];
            uint32_t al2 = *(uint32_t*)&AsL[mrow + gq][kk + 2 * tg + 8];
            uint32_t al3 = *(uint32_t*)&AsL[mrow + gq + 8][kk + 2 * tg + 8];
#pragma unroll
            for (int nf = 0; nf < 4; nf++) {
                int n = nq + nf * 8 + gq;
                uint32_t bh0 = *(uint32_t*)&BsH[n][kk + 2 * tg];
                uint32_t bh1 = *(uint32_t*)&BsH[n][kk + 2 * tg + 8];
                uint32_t bl0 = *(uint32_t*)&BsL[n][kk + 2 * tg];
                uint32_t bl1 = *(uint32_t*)&BsL[n][kk + 2 * tg + 8];
                mma16816(acc[nf], ah0, ah1, ah2, ah3, bh0, bh1);
                mma16816(acc[nf], al0, al1, al2, al3, bh0, bh1);
                mma16816(acc[nf], ah0, ah1, ah2, ah3, bl0, bl1);
            }
        }
        __syncthreads();
    }

#pragma unroll
    for (int nf = 0; nf < 4; nf++) {
        int col = n0 + nq + nf * 8 + 2 * tg;
        float bs0 = bias1[col] + bias2[col];
        float bs1 = bias1[col + 1] + bias2[col + 1];
        int r0 = m0 + mrow + gq;
        g_xp[(size_t)r0 * GG + col] = acc[nf][0] + bs0;
        g_xp[(size_t)r0 * GG + col + 1] = acc[nf][1] + bs1;
        g_xp[(size_t)(r0 + 8) * GG + col] = acc[nf][2] + bs0;
        g_xp[(size_t)(r0 + 8) * GG + col + 1] = acc[nf][3] + bs1;
    }
}

// ---------------- persistent recurrence (fp16, 2-term), 128 CTAs x 256 thr ----------------
// CTA owns 8 h-cols (32 gate rows). W_hh slice resident in SMEM as fp16 hi+lo
// (exact). h streamed as a SINGLE fp16 plane per 128-wide chunk, 4 stage
// buffers, pipeline depth 3, ONE syncthreads per chunk.
// 8 warps = 2 m-warps (m32) x 4 k-groups (k-slice 32); warp tile m32 x n32.
// Gates = h.(Wh+Wl): 2 MMAs per fragment pair. 3 partial sets; set0 = Gs.
__global__ __launch_bounds__(NT, 1) void recur_kernel(const float* __restrict__ w_hh) {
    extern __shared__ unsigned char smem[];
    __half* Wh = (__half*)(smem + OFF_WH);
    __half* Wl = (__half*)(smem + OFF_WH + 66048);
    __half* Hs = (__half*)(smem + OFF_HS);      // 4 bufs of 64*RS_C2
    float* PS = (float*)(smem + OFF_PS);        // 3 sets; set0 = Gs
    float* Cs = (float*)(smem + OFF_CS);

    int tid = threadIdx.x;
    int j0 = blockIdx.x * 8;

    // Preload resident W slice (both planes), split from fp32
    for (int idx = tid; idx < 32 * 1024; idx += NT) {
        int r = idx >> 10, k = idx & 1023;
        int q = r >> 3, i = r & 7;
        float v = w_hh[(size_t)(q * HH + j0 + i) * HH + k];
        __half hi, lo;
        split_f16(v, hi, lo);
        Wh[r * RS_W2 + k] = hi;
        Wl[r * RS_W2 + k] = lo;
    }
    for (int idx = tid; idx < 512; idx += NT) Cs[idx] = 0.f;
    __syncthreads();

    int lane = tid & 31, wid = tid >> 5;
    int gq = lane >> 2, tg = lane & 3;
    int mw = wid & 1;            // m half: batch rows [mw*32, mw*32+32)
    int kg = wid >> 1;           // k-group 0..3: k-slice kg*32 within chunk
    int rb = mw * 32 + gq;       // fragment base row (mf adds 16)
    int kks = kg * 32;

    for (int t = 0; t < TT; t++) {
        // step barrier: wait for all CTAs to have finished step t-1
        if (t > 0) {
            if (tid < NCTA) {
                while (g_flags[tid * 32] < (unsigned)t) {}
            }
            __syncthreads();
        }

        const __half* rbuf = g_hbuf[(t + 1) & 1];
        __half* wbuf = g_hbuf[t & 1];
        const float* xpt = g_xp + (size_t)t * BB * GG;

        // prefetch this thread's xp gates into registers (2 cell elems/thread)
        float xg[2][4];
#pragma unroll
        for (int u = 0; u < 2; u++) {
            int e = tid + u * NT;
            int ub = e >> 3, ui = e & 7;
            xg[u][0] = __ldg(xpt + (size_t)ub * GG + j0 + ui);
            xg[u][1] = __ldg(xpt + (size_t)ub * GG + HH + j0 + ui);
            xg[u][2] = __ldg(xpt + (size_t)ub * GG + 2 * HH + j0 + ui);
            xg[u][3] = __ldg(xpt + (size_t)ub * GG + 3 * HH + j0 + ui);
        }

        float acc[2][4][4];
#pragma unroll
        for (int a = 0; a < 2; a++)
#pragma unroll
            for (int b = 0; b < 4; b++)
#pragma unroll
                for (int c = 0; c < 4; c++) acc[a][b][c] = 0.f;

        // pre-issue chunks 0..2 (single h plane: 1024 cp.async16 per chunk)
#pragma unroll
        for (int c = 0; c < 3; c++) {
            __half* dst = Hs + c * (64 * RS_C2);
#pragma unroll
            for (int s = tid; s < 1024; s += NT) {
                int r = s >> 4, seg = s & 15;
                cp_async16(dst + r * RS_C2 + seg * 8,
                           rbuf + (size_t)r * HH + c * CH2 + seg * 8);
            }
            CP_COMMIT();
        }

        for (int ci = 0; ci < NCH2; ci++) {
            CP_WAIT(2);
            __syncthreads();

            const __half* hS = Hs + (ci & 3) * (64 * RS_C2);
#pragma unroll
            for (int kk = 0; kk < 32; kk += 16) {
                int kl = kks + kk;               // k within chunk
                int kw = ci * CH2 + kl;          // global k for resident W
                uint32_t ah[2][4];
#pragma unroll
                for (int mf = 0; mf < 2; mf++) {
                    int r0 = rb + mf * 16;
                    ah[mf][0] = *(uint32_t*)&hS[r0 * RS_C2 + kl + 2 * tg];
                    ah[mf][1] = *(uint32_t*)&hS[(r0 + 8) * RS_C2 + kl + 2 * tg];
                    ah[mf][2] = *(uint32_t*)&hS[r0 * RS_C2 + kl + 2 * tg + 8];
                    ah[mf][3] = *(uint32_t*)&hS[(r0 + 8) * RS_C2 + kl + 2 * tg + 8];
                }
#pragma unroll
                for (int nf = 0; nf < 4; nf++) {
                    int n = nf * 8 + gq;
                    uint32_t bh0 = *(uint32_t*)&Wh[n * RS_W2 + kw + 2 * tg];
                    uint32_t bh1 = *(uint32_t*)&Wh[n * RS_W2 + kw + 2 * tg + 8];
                    uint32_t bl0 = *(uint32_t*)&Wl[n * RS_W2 + kw + 2 * tg];
                    uint32_t bl1 = *(uint32_t*)&Wl[n * RS_W2 + kw + 2 * tg + 8];
#pragma unroll
                    for (int mf = 0; mf < 2; mf++) {
                        mma16816(acc[mf][nf], ah[mf][0], ah[mf][1], ah[mf][2], ah[mf][3], bh0, bh1);
                        mma16816(acc[mf][nf], ah[mf][0], ah[mf][1], ah[mf][2], ah[mf][3], bl0, bl1);
                    }
                }
            }

            // issue chunk ci+3 into buffer (ci+3)&3 (released by this iter's sync)
            if (ci + 3 < NCH2) {
                int kc = (ci + 3) * CH2;
                __half* dst = Hs + ((ci + 3) & 3) * (64 * RS_C2);
#pragma unroll
                for (int s = tid; s < 1024; s += NT) {
                    int r = s >> 4, seg = s & 15;
                    cp_async16(dst + r * RS_C2 + seg * 8,
                               rbuf + (size_t)r * HH + kc + seg * 8);
                }
            }
            CP_COMMIT();   // uniform group count (possibly empty)
        }

        // k-group reduction: kg=1,2,3 dump partials, kg=0 combines into PS set0
        if (kg != 0) {
            float* P = PS + (kg - 1) * 64 * RS_G;
#pragma unroll
            for (int mf = 0; mf < 2; mf++) {
                int r0 = rb + mf * 16;
#pragma unroll
                for (int nf = 0; nf < 4; nf++) {
                    int col = nf * 8 + 2 * tg;
                    P[r0 * RS_G + col] = acc[mf][nf][0];
                    P[r0 * RS_G + col + 1] = acc[mf][nf][1];
                    P[(r0 + 8) * RS_G + col] = acc[mf][nf][2];
                    P[(r0 + 8) * RS_G + col + 1] = acc[mf][nf][3];
                }
            }
        }
        __syncthreads();
        if (kg == 0) {
            float* P1 = PS;                   // also the output (Gs)
            float* P2 = PS + 1 * 64 * RS_G;
            float* P3 = PS + 2 * 64 * RS_G;
#pragma unroll
            for (int mf = 0; mf < 2; mf++) {
                int r0 = rb + mf * 16;
#pragma unroll
                for (int nf = 0; nf < 4; nf++) {
                    int col = nf * 8 + 2 * tg;
                    int a0 = r0 * RS_G + col, a1 = r0 * RS_G + col + 1;
                    int a2 = (r0 + 8) * RS_G + col, a3 = (r0 + 8) * RS_G + col + 1;
                    P1[a0] = acc[mf][nf][0] + P1[a0] + P2[a0] + P3[a0];
                    P1[a1] = acc[mf][nf][1] + P1[a1] + P2[a1] + P3[a1];
                    P1[a2] = acc[mf][nf][2] + P1[a2] + P2[a2] + P3[a2];
                    P1[a3] = acc[mf][nf][3] + P1[a3] + P2[a3] + P3[a3];
                }
            }
        }
        __syncthreads();

        // cell update: 512 elems, 2 per thread (Gs = PS set0)
        {
            const float* Gs = PS;
#pragma unroll
            for (int u = 0; u < 2; u++) {
                int e = tid + u * NT;
                int ub = e >> 3, ui = e & 7;
                float gi = Gs[ub * RS_G + ui]      + xg[u][0];
                float gf = Gs[ub * RS_G + 8 + ui]  + xg[u][1];
                float gg = Gs[ub * RS_G + 16 + ui] + xg[u][2];
                float go = Gs[ub * RS_G + 24 + ui] + xg[u][3];
                float si = sigmoid_f(gi);
                float sf = sigmoid_f(gf);
                float sg = tanh_f(gg);
                float so = sigmoid_f(go);
                float c = sf * Cs[e] + si * sg;
                Cs[e] = c;
                float h = so * tanh_f(c);
                __half hi, lo;
                split_f16(h, hi, lo);
                wbuf[(size_t)ub * HH + j0 + ui] = hi;   // stream plane (single)
                size_t so2 = ((size_t)t * BB + ub) * HH + j0 + ui;
                g_hseq_h[so2] = hi;                     // exact pair for gemm/final
                g_hseq_l[so2] = lo;
            }
        }
        __syncthreads();

        // publish completion of step t (release)
        if (tid == 0) {
            __threadfence();
            g_flags[blockIdx.x * 32] = (unsigned)(t + 1);
        }
    }
}

// ---------------- final linear ----------------
__global__ void final_kernel(const float* __restrict__ w_lin,
                             const float* __restrict__ b_lin,
                             float* __restrict__ out) {
    int b = blockIdx.x;
    __shared__ float red[256];
    float s = 0.f;
    size_t base = ((size_t)(TT - 1) * BB + b) * HH;
    for (int i = threadIdx.x; i < HH; i += 256) {
        float h = __half2float(g_hseq_h[base + i]) + __half2float(g_hseq_l[base + i]);
        s += h * w_lin[i];
    }
    red[threadIdx.x] = s;
    __syncthreads();
    for (int st = 128; st > 0; st >>= 1) {
        if (threadIdx.x < st) red[threadIdx.x] += red[threadIdx.x + st];
        __syncthreads();
    }
    if (threadIdx.x == 0) out[b] = red[0] + b_lin[0];
}

// ---------------- launch ----------------
extern "C" void kernel_launch(void* const* d_in, const int* in_sizes, int n_in,
                              void* d_out, int out_size) {
    const float* x     = (const float*)d_in[0];
    const float* w_ih0 = (const float*)d_in[1];
    const float* w_hh0 = (const float*)d_in[2];
    const float* b_ih0 = (const float*)d_in[3];
    const float* b_hh0 = (const float*)d_in[4];
    const float* w_ih1 = (const float*)d_in[5];
    const float* w_hh1 = (const float*)d_in[6];
    const float* b_ih1 = (const float*)d_in[7];
    const float* b_hh1 = (const float*)d_in[8];
    const float* w_lin = (const float*)d_in[9];
    const float* b_lin = (const float*)d_in[10];
    float* out = (float*)d_out;

    cudaFuncSetAttribute(recur_kernel, cudaFuncAttributeMaxDynamicSharedMemorySize,
                         SMEM_RECUR);

    // layer 0
    prep_kernel<<<256, 256>>>();
    convert_x_kernel<<<2048, 256>>>(x);
    convert_wih_kernel<<<1024, 256>>>(w_ih0, GG * DD);
    gemm_kernel<<<dim3(64, 512), 256>>>(0, DD, b_ih0, b_hh0);
    recur_kernel<<<NCTA, NT, SMEM_RECUR>>>(w_hh0);

    // layer 1
    prep_kernel<<<256, 256>>>();
    convert_wih_kernel<<<4096, 256>>>(w_ih1, GG * HH);
    gemm_kernel<<<dim3(64, 512), 256>>>(1, HH, b_ih1, b_hh1);
    recur_kernel<<<NCTA, NT, SMEM_RECUR>>>(w_hh1);

    // output head
    final_kernel<<<64, 256>>>(w_lin, b_lin, out);
}